// round 1
// baseline (speedup 1.0000x reference)
#include <cuda_runtime.h>
#include <math.h>
#include <float.h>

#define Bb   2
#define Cc   2048
#define Dd   1024
#define Hh   16
#define HDd  64
#define ROWS (Bb*Cc)   // 4096

// ---------------- scratch (static device allocations; no cudaMalloc) ----------------
__device__ float g_xn[ROWS*Dd];           // layernorm output        16 MB
__device__ float g_q [ROWS*Dd];           // q projection            16 MB
__device__ float g_kv[ROWS*2*Dd];         // kv projection           32 MB
__device__ float g_Q [Bb*Hh*Cc*HDd];      // roped Q  [b,h,c,d]      16 MB
__device__ float g_K [Bb*Hh*Cc*HDd];      // roped K                 16 MB
__device__ float g_V [Bb*Hh*Cc*HDd];      // V                       16 MB
__device__ float g_sc[Bb*Hh*Cc];          // per-key scale
__device__ float g_vsum[Bb*Hh*HDd];       // sum_j V[j]
__device__ float g_wv[ROWS*Dd];           // attention out (b,c,dims) 16 MB
__device__ float g_freqs[HDd/2];          // theta/220 * freqs_base

// ---------------- freqs: match numpy double math exactly, cast to fp32 --------------
__global__ void init_freqs_kernel(const float* __restrict__ theta){
    int i = threadIdx.x;
    if (i < 32){
        double E = 2595.0 * log10(21.0);               // 2595*log10(1+4000/200)
        double v = (i == 31) ? E : (E/31.0) * (double)i; // np.linspace semantics
        double mel = pow(10.0, v/2595.0) - 1.0;
        float fb = (float)(200.0 * mel / 1000.0);
        g_freqs[i] = (theta[0] / 220.0f) * fb;          // fp32 like jnp
    }
}

// ---------------- layernorm: one block per row of 1024 ------------------------------
__global__ void __launch_bounds__(256) ln_kernel(const float* __restrict__ x,
                                                 const float* __restrict__ lw,
                                                 const float* __restrict__ lb){
    int row = blockIdx.x;
    int t = threadIdx.x;
    const float4* xr = (const float4*)(x + (size_t)row * Dd);
    float4 v = xr[t];
    float s  = v.x + v.y + v.z + v.w;
    float s2 = v.x*v.x + v.y*v.y + v.z*v.z + v.w*v.w;
    __shared__ float shs[8], shs2[8], mv[2];
    #pragma unroll
    for (int o = 16; o > 0; o >>= 1){
        s  += __shfl_down_sync(0xffffffffu, s,  o);
        s2 += __shfl_down_sync(0xffffffffu, s2, o);
    }
    if ((t & 31) == 0){ shs[t>>5] = s; shs2[t>>5] = s2; }
    __syncthreads();
    if (t == 0){
        float a = 0.f, b2 = 0.f;
        #pragma unroll
        for (int i = 0; i < 8; i++){ a += shs[i]; b2 += shs2[i]; }
        float mu  = a  * (1.0f/Dd);
        float var = b2 * (1.0f/Dd) - mu*mu;
        mv[0] = mu; mv[1] = rsqrtf(var + 1e-5f);
    }
    __syncthreads();
    float mu = mv[0], rstd = mv[1];
    float4 w4 = ((const float4*)lw)[t];
    float4 b4 = ((const float4*)lb)[t];
    float4 o;
    o.x = (v.x - mu) * rstd * w4.x + b4.x;
    o.y = (v.y - mu) * rstd * w4.y + b4.y;
    o.z = (v.z - mu) * rstd * w4.z + b4.z;
    o.w = (v.w - mu) * rstd * w4.w + b4.w;
    ((float4*)(g_xn + (size_t)row * Dd))[t] = o;
}

// ---------------- SGEMM: C[M,N] = A[M,K] * B[N,K]^T  (128x128x8, 8x8/thread) --------
__global__ void __launch_bounds__(256) sgemm_nt(const float* __restrict__ A,
                                                const float* __restrict__ Bw,
                                                float* __restrict__ Co,
                                                int M, int N, int K){
    __shared__ float As[8][128];
    __shared__ float Bs[8][128];
    int tid = threadIdx.x;
    int m0 = blockIdx.y * 128;
    int n0 = blockIdx.x * 128;
    int lr = tid >> 1;            // 0..127
    int lh = (tid & 1) * 4;       // 0 or 4
    int ty = tid >> 4, tx = tid & 15;
    float acc[8][8];
    #pragma unroll
    for (int i = 0; i < 8; i++)
        #pragma unroll
        for (int j = 0; j < 8; j++) acc[i][j] = 0.f;

    const float* Ap = A  + (size_t)(m0 + lr) * K + lh;
    const float* Bp = Bw + (size_t)(n0 + lr) * K + lh;

    for (int k0 = 0; k0 < K; k0 += 8){
        float4 av = *(const float4*)(Ap + k0);
        float4 bv = *(const float4*)(Bp + k0);
        As[lh+0][lr] = av.x; As[lh+1][lr] = av.y; As[lh+2][lr] = av.z; As[lh+3][lr] = av.w;
        Bs[lh+0][lr] = bv.x; Bs[lh+1][lr] = bv.y; Bs[lh+2][lr] = bv.z; Bs[lh+3][lr] = bv.w;
        __syncthreads();
        #pragma unroll
        for (int k = 0; k < 8; k++){
            float a[8], b[8];
            *(float4*)(a)   = *(const float4*)&As[k][ty*8];
            *(float4*)(a+4) = *(const float4*)&As[k][ty*8+4];
            *(float4*)(b)   = *(const float4*)&Bs[k][tx*8];
            *(float4*)(b+4) = *(const float4*)&Bs[k][tx*8+4];
            #pragma unroll
            for (int i = 0; i < 8; i++)
                #pragma unroll
                for (int j = 0; j < 8; j++)
                    acc[i][j] = fmaf(a[i], b[j], acc[i][j]);
        }
        __syncthreads();
    }
    #pragma unroll
    for (int i = 0; i < 8; i++){
        float* crow = Co + (size_t)(m0 + ty*8 + i) * N + n0 + tx*8;
        #pragma unroll
        for (int j = 0; j < 8; j += 4){
            float4 o = { acc[i][j], acc[i][j+1], acc[i][j+2], acc[i][j+3] };
            *(float4*)(crow + j) = o;
        }
    }
}

// ---------------- RoPE + head split (+sc) -------------------------------------------
__global__ void rope_kernel(){
    int idx = blockIdx.x * blockDim.x + threadIdx.x;  // B*H*C*32 threads
    int m = idx & 31;
    int t = idx >> 5;
    int h = t & (Hh-1); t >>= 4;
    int c = t & (Cc-1);
    int b = t >> 11;
    float f   = g_freqs[m];
    float ang = (float)c * f;           // fp32 multiply, same as reference
    float sn = sinf(ang), cs = cosf(ang);
    size_t qoff  = ((size_t)(b*Cc + c)) * Dd     + h*HDd + 2*m;
    size_t kvoff = ((size_t)(b*Cc + c)) * (2*Dd) + h*HDd + 2*m;
    float qe = g_q[qoff],        qo = g_q[qoff+1];
    float ke = g_kv[kvoff],      ko = g_kv[kvoff+1];
    float ve = g_kv[kvoff + Dd], vo = g_kv[kvoff + Dd + 1];
    size_t ooff = ((size_t)((b*Hh + h)*Cc + c)) * HDd + 2*m;
    g_Q[ooff]   = qe*cs - qo*sn;
    g_Q[ooff+1] = qe*sn + qo*cs;
    float k0 = ke*cs - ko*sn;
    g_K[ooff]   = k0;
    g_K[ooff+1] = ke*sn + ko*cs;
    g_V[ooff]   = ve;
    g_V[ooff+1] = vo;
    if (m == 0) g_sc[(b*Hh + h)*Cc + c] = (k0 == 0.0f) ? 1e-5f : 1.0f;
}

// ---------------- Vsum per (b,h) -----------------------------------------------------
__global__ void __launch_bounds__(256) vsum_kernel(){
    int bh = blockIdx.x;
    int t = threadIdx.x;
    int d = t & 63, sl = t >> 6;                       // 4 slices of 512 keys
    const float* Vp = g_V + ((size_t)bh*Cc + sl*512) * HDd + d;
    float s = 0.f;
    #pragma unroll 8
    for (int j = 0; j < 512; j++) s += Vp[(size_t)j * HDd];
    __shared__ float sh[256];
    sh[t] = s;
    __syncthreads();
    if (t < 64)
        g_vsum[bh*64 + t] = sh[t] + sh[t+64] + sh[t+128] + sh[t+192];
}

// ---------------- attention: 64q x 64k tiles, causal only + Vsum rescue -------------
__global__ void __launch_bounds__(256) attn_kernel(const int* __restrict__ use_mask_p){
    extern __shared__ float sm[];
    float* Qs   = sm;                 // 64 x 65
    float* Ks   = sm + 64*65;         // 64 x 65 (reused as W tile)
    float* Vs   = sm + 2*64*65;       // 64 x 64
    float* rsum = Vs + 64*64;         // 64
    float* scs  = rsum + 64;          // 64

    int tid = threadIdx.x;
    int qb = blockIdx.x, bh = blockIdx.y;
    int b = bh >> 4, h = bh & 15;
    int i0 = qb * 64;
    int umask = use_mask_p[0];

    const float* Qg = g_Q + ((size_t)bh*Cc + i0) * HDd;
    for (int v = tid; v < 1024; v += 256){
        int r = v >> 4, c4 = (v & 15) * 4;
        float4 q4 = *(const float4*)(Qg + r*HDd + c4);
        Qs[r*65+c4] = q4.x; Qs[r*65+c4+1] = q4.y; Qs[r*65+c4+2] = q4.z; Qs[r*65+c4+3] = q4.w;
    }
    if (tid < 64) rsum[tid] = 0.f;

    float acc[4][4];
    #pragma unroll
    for (int i = 0; i < 4; i++)
        #pragma unroll
        for (int j = 0; j < 4; j++) acc[i][j] = 0.f;

    int ty = tid >> 4, tx = tid & 15;
    int r0 = ty*4, c0 = tx*4;
    int kb_last = umask ? qb : (Cc/64 - 1);

    for (int kb = 0; kb <= kb_last; kb++){
        int j0 = kb * 64;
        __syncthreads();   // previous iteration done with Ks/Vs; also covers Qs first time
        const float* Kg = g_K + ((size_t)bh*Cc + j0) * HDd;
        const float* Vg = g_V + ((size_t)bh*Cc + j0) * HDd;
        for (int v = tid; v < 1024; v += 256){
            int r = v >> 4, c4 = (v & 15) * 4;
            float4 k4 = *(const float4*)(Kg + r*HDd + c4);
            Ks[r*65+c4] = k4.x; Ks[r*65+c4+1] = k4.y; Ks[r*65+c4+2] = k4.z; Ks[r*65+c4+3] = k4.w;
            float4 v4 = *(const float4*)(Vg + r*HDd + c4);
            *(float4*)(Vs + r*64 + c4) = v4;
        }
        if (tid < 64) scs[tid] = g_sc[(size_t)bh*Cc + j0 + tid];
        __syncthreads();

        // S = Q K^T
        float sv[4][4];
        #pragma unroll
        for (int i = 0; i < 4; i++)
            #pragma unroll
            for (int j = 0; j < 4; j++) sv[i][j] = 0.f;
        #pragma unroll 8
        for (int d = 0; d < 64; d++){
            float qr[4], kc[4];
            #pragma unroll
            for (int i = 0; i < 4; i++) qr[i] = Qs[(r0+i)*65 + d];
            #pragma unroll
            for (int j = 0; j < 4; j++) kc[j] = Ks[(c0+j)*65 + d];
            #pragma unroll
            for (int i = 0; i < 4; i++)
                #pragma unroll
                for (int j = 0; j < 4; j++)
                    sv[i][j] = fmaf(qr[i], kc[j], sv[i][j]);
        }
        __syncthreads();   // all Ks reads done; safe to overwrite as W

        #pragma unroll
        for (int i = 0; i < 4; i++){
            int ig = i0 + r0 + i;
            #pragma unroll
            for (int j = 0; j < 4; j++){
                int jg = j0 + c0 + j;
                float scj = scs[c0+j];
                float val = sv[i][j] * 0.125f;
                if (umask){
                    if (jg > ig) val = -FLT_MAX;
                    val *= scj;
                    val = 1.0f / (1.0f + expf(-val));   // sigmoid(-FLT_MAX)=0 -> w=0
                }
                val *= scj;
                float w = val + 0.5f*val*val;           // num - 1
                Ks[(r0+i)*65 + (c0+j)] = w;
            }
        }
        __syncthreads();

        if (tid < 64){
            float rs = 0.f;
            #pragma unroll 8
            for (int j = 0; j < 64; j++) rs += Ks[tid*65 + j];
            rsum[tid] += rs;
        }
        // P @ V
        #pragma unroll 8
        for (int jc = 0; jc < 64; jc++){
            float wr[4], vc[4];
            #pragma unroll
            for (int i = 0; i < 4; i++) wr[i] = Ks[(r0+i)*65 + jc];
            #pragma unroll
            for (int j = 0; j < 4; j++) vc[j] = Vs[jc*64 + c0 + j];
            #pragma unroll
            for (int i = 0; i < 4; i++)
                #pragma unroll
                for (int j = 0; j < 4; j++)
                    acc[i][j] = fmaf(wr[i], vc[j], acc[i][j]);
        }
    }
    __syncthreads();

    const float* vs = g_vsum + bh*64;
    #pragma unroll
    for (int i = 0; i < 4; i++){
        int ig = i0 + r0 + i;
        float den = (float)Cc + rsum[r0+i];
        #pragma unroll
        for (int j = 0; j < 4; j++){
            float o = (vs[c0+j] + acc[i][j]) / den;
            g_wv[((size_t)(b*Cc + ig)) * Dd + h*HDd + c0 + j] = o;
        }
    }
}

// ---------------- launch -------------------------------------------------------------
extern "C" void kernel_launch(void* const* d_in, const int* in_sizes, int n_in,
                              void* d_out, int out_size){
    const float* x    = (const float*)d_in[0];
    const float* lw   = (const float*)d_in[1];
    const float* lb   = (const float*)d_in[2];
    const float* Wq   = (const float*)d_in[3];
    const float* Wkv  = (const float*)d_in[4];
    const float* Wout = (const float*)d_in[5];
    const float* th   = (const float*)d_in[6];
    const int*   um   = (const int*)d_in[7];
    float* out = (float*)d_out;

    void *pxn = 0, *pq = 0, *pkv = 0, *pwv = 0;
    cudaGetSymbolAddress(&pxn, g_xn);
    cudaGetSymbolAddress(&pq,  g_q);
    cudaGetSymbolAddress(&pkv, g_kv);
    cudaGetSymbolAddress(&pwv, g_wv);

    const int ATT_SMEM = (2*64*65 + 64*64 + 128) * 4;  // 50176 B
    cudaFuncSetAttribute(attn_kernel, cudaFuncAttributeMaxDynamicSharedMemorySize, ATT_SMEM);

    init_freqs_kernel<<<1, 32>>>(th);
    ln_kernel<<<ROWS, 256>>>(x, lw, lb);
    sgemm_nt<<<dim3(Dd/128,   ROWS/128), 256>>>((const float*)pxn, Wq,  (float*)pq,  ROWS, Dd,   Dd);
    sgemm_nt<<<dim3(2*Dd/128, ROWS/128), 256>>>((const float*)pxn, Wkv, (float*)pkv, ROWS, 2*Dd, Dd);
    rope_kernel<<<(Bb*Hh*Cc*32)/256, 256>>>();
    vsum_kernel<<<Bb*Hh, 256>>>();
    attn_kernel<<<dim3(Cc/64, Bb*Hh), 256, ATT_SMEM>>>(um);
    sgemm_nt<<<dim3(Dd/128, ROWS/128), 256>>>((const float*)pwv, Wout, out, ROWS, Dd, Dd);
}

// round 4
// speedup vs baseline: 1.6102x; 1.6102x over previous
#include <cuda_runtime.h>
#include <cuda_bf16.h>
#include <math.h>
#include <float.h>
#include <stdint.h>

#define Bb   2
#define Cc   2048
#define Dd   1024
#define Hh   16
#define HDd  64
#define ROWS (Bb*Cc)   // 4096

typedef __nv_bfloat16 bf16;

// ---------------- scratch ----------------
__device__ float g_q [ROWS*Dd];
__device__ float g_kv[ROWS*2*Dd];
__device__ float g_Q [Bb*Hh*Cc*HDd];
__device__ float g_K [Bb*Hh*Cc*HDd];
__device__ float g_V [Bb*Hh*Cc*HDd];
__device__ float g_sc[Bb*Hh*Cc];
__device__ float g_vsum[Bb*Hh*HDd];
__device__ float g_wv[ROWS*Dd];
__device__ float g_freqs[HDd/2];

__device__ bf16 g_xnh[ROWS*Dd],  g_xnl[ROWS*Dd];
__device__ bf16 g_wvh[ROWS*Dd],  g_wvl[ROWS*Dd];
__device__ bf16 g_Wqh[Dd*Dd],    g_Wql[Dd*Dd];
__device__ bf16 g_Wkvh[2*Dd*Dd], g_Wkvl[2*Dd*Dd];
__device__ bf16 g_Woh[Dd*Dd],    g_Wol[Dd*Dd];

// ================= PTX helpers (baseline compute_100: mma.sync/ldmatrix/cp.async) ===
__device__ __forceinline__ uint32_t smem_u32(const void* p){
    uint32_t a;
    asm("{ .reg .u64 t; cvta.to.shared.u64 t, %1; cvt.u32.u64 %0, t; }" : "=r"(a) : "l"(p));
    return a;
}
#define CP16(dst, src) asm volatile("cp.async.cg.shared.global [%0], [%1], 16;" :: "r"(dst), "l"(src) : "memory")
#define CP_COMMIT()    asm volatile("cp.async.commit_group;" ::: "memory")
#define CP_WAIT(n)     asm volatile("cp.async.wait_group %0;" :: "n"(n) : "memory")
#define LDSM4(r, a) asm volatile("ldmatrix.sync.aligned.m8n8.x4.shared.b16 {%0,%1,%2,%3}, [%4];" \
  : "=r"((r)[0]),"=r"((r)[1]),"=r"((r)[2]),"=r"((r)[3]) : "r"(a))
#define MMA4(c, a, b0, b1) asm volatile( \
  "mma.sync.aligned.m16n8k16.row.col.f32.bf16.bf16.f32 {%0,%1,%2,%3}, {%4,%5,%6,%7}, {%8,%9}, {%0,%1,%2,%3};" \
  : "+f"((c)[0]),"+f"((c)[1]),"+f"((c)[2]),"+f"((c)[3]) \
  : "r"((a)[0]),"r"((a)[1]),"r"((a)[2]),"r"((a)[3]), "r"(b0),"r"(b1))

__device__ __forceinline__ uint32_t pk_hi(float x, float y, float& lx, float& ly){
    bf16 hx = __float2bfloat16(x);
    bf16 hy = __float2bfloat16(y);
    lx = x - __bfloat162float(hx);
    ly = y - __bfloat162float(hy);
    return (uint32_t)__bfloat16_as_ushort(hx) | ((uint32_t)__bfloat16_as_ushort(hy) << 16);
}
__device__ __forceinline__ uint32_t pk(float x, float y){
    bf16 hx = __float2bfloat16(x);
    bf16 hy = __float2bfloat16(y);
    return (uint32_t)__bfloat16_as_ushort(hx) | ((uint32_t)__bfloat16_as_ushort(hy) << 16);
}

// ---------------- fp32 -> bf16 hi/lo split ------------------------------------------
__global__ void __launch_bounds__(256) cvt_kernel(const float* __restrict__ src,
                                                  bf16* __restrict__ h, bf16* __restrict__ l){
    int i = blockIdx.x * 256 + threadIdx.x;
    float4 a = ((const float4*)src)[i];
    float lx, ly, lz, lw;
    uint32_t h01 = pk_hi(a.x, a.y, lx, ly);
    uint32_t h23 = pk_hi(a.z, a.w, lz, lw);
    ((uint2*)h)[i] = make_uint2(h01, h23);
    ((uint2*)l)[i] = make_uint2(pk(lx, ly), pk(lz, lw));
}

// ================= bf16x3 mma.sync GEMM: C[M,N] = A[M,1024] * B[N,1024]^T ==========
// block 256 thr (8 warps, 2x4), tile M128 N128, K-chunk 64, 2-stage cp.async pipeline
// stage: Ah 16K | Al 16K | Bh 16K | Bl 16K  (rows of 64 bf16 = 128B, XOR-swizzled)
#define GEMM_SMEM (2*65536)

__device__ __forceinline__ void issue_stage(uint32_t sb, int s, int c, int tid,
                                            const bf16* Ah, const bf16* Al,
                                            const bf16* Bh, const bf16* Bl,
                                            int m0, int n0){
    const bf16* srcs[4] = {Ah, Al, Bh, Bl};
    #pragma unroll
    for (int bufi = 0; bufi < 4; bufi++){
        int row0 = (bufi < 2) ? m0 : n0;
        const bf16* S = srcs[bufi];
        uint32_t dstb = sb + s*65536 + bufi*16384;
        #pragma unroll
        for (int it = 0; it < 4; it++){
            int i = tid + it*256;
            int r  = i >> 3;
            int cb = (i & 7) * 16;          // bytes within 128B row
            uint32_t bo = (uint32_t)(r*128 + cb);
            uint32_t dst = dstb + (bo ^ ((bo >> 3) & 0x70));
            const char* src = (const char*)(S + (size_t)(row0 + r)*1024 + c*64) + cb;
            CP16(dst, src);
        }
    }
}

__global__ void __launch_bounds__(256) gemm_mma(const bf16* __restrict__ Ah,
                                                const bf16* __restrict__ Al,
                                                const bf16* __restrict__ Bh,
                                                const bf16* __restrict__ Bl,
                                                float* __restrict__ C, int N){
    extern __shared__ __align__(1024) char smem[];
    uint32_t sb = smem_u32(smem);
    int tid = threadIdx.x, lane = tid & 31, wid = tid >> 5;
    int m0 = blockIdx.y * 128, n0 = blockIdx.x * 128;
    int wm = (wid >> 2) * 64;     // 0 or 64
    int wn = (wid & 3) * 32;      // 0,32,64,96

    float acc[4][4][4];
    #pragma unroll
    for (int a = 0; a < 4; a++)
        #pragma unroll
        for (int b = 0; b < 4; b++)
            #pragma unroll
            for (int c = 0; c < 4; c++) acc[a][b][c] = 0.f;

    issue_stage(sb, 0, 0, tid, Ah, Al, Bh, Bl, m0, n0);
    CP_COMMIT();

    #pragma unroll 1
    for (int c = 0; c < 16; c++){
        if (c + 1 < 16){
            issue_stage(sb, (c+1)&1, c+1, tid, Ah, Al, Bh, Bl, m0, n0);
            CP_COMMIT();
            CP_WAIT(1);
        } else {
            CP_WAIT(0);
        }
        __syncthreads();

        uint32_t sA = sb + (c&1)*65536;
        uint32_t sB = sA + 32768;
        #pragma unroll
        for (int ks = 0; ks < 4; ks++){
            uint32_t ahf[4][4], alf[4][4], bhf[2][4], blf[2][4];
            #pragma unroll
            for (int mt = 0; mt < 4; mt++){
                int r    = wm + mt*16 + (lane & 7) + ((lane >> 3) & 1)*8;
                int koff = ks*32 + (lane >> 4)*16;
                uint32_t bo = (uint32_t)(r*128 + koff);
                uint32_t sw = bo ^ ((bo >> 3) & 0x70);
                LDSM4(ahf[mt], sA + sw);
                LDSM4(alf[mt], sA + 16384 + sw);
            }
            #pragma unroll
            for (int p = 0; p < 2; p++){
                int r    = wn + p*16 + ((lane >> 4) & 1)*8 + (lane & 7);
                int koff = ks*32 + ((lane >> 3) & 1)*16;
                uint32_t bo = (uint32_t)(r*128 + koff);
                uint32_t sw = bo ^ ((bo >> 3) & 0x70);
                LDSM4(bhf[p], sB + sw);
                LDSM4(blf[p], sB + 16384 + sw);
            }
            #pragma unroll
            for (int mt = 0; mt < 4; mt++)
                #pragma unroll
                for (int nt = 0; nt < 4; nt++){
                    int p = nt >> 1, s2 = nt & 1;
                    MMA4(acc[mt][nt], ahf[mt], bhf[p][s2*2], bhf[p][s2*2+1]);
                    MMA4(acc[mt][nt], ahf[mt], blf[p][s2*2], blf[p][s2*2+1]);
                    MMA4(acc[mt][nt], alf[mt], bhf[p][s2*2], bhf[p][s2*2+1]);
                }
        }
        __syncthreads();
    }

    // epilogue: c-frag m16n8 mapping -> direct float2 stores
    #pragma unroll
    for (int mt = 0; mt < 4; mt++){
        #pragma unroll
        for (int nt = 0; nt < 4; nt++){
            int row = m0 + wm + mt*16 + (lane >> 2);
            int col = n0 + wn + nt*8  + (lane & 3)*2;
            float2 v0 = { acc[mt][nt][0], acc[mt][nt][1] };
            float2 v1 = { acc[mt][nt][2], acc[mt][nt][3] };
            *(float2*)(C + (size_t)row*N + col)     = v0;
            *(float2*)(C + (size_t)(row+8)*N + col) = v1;
        }
    }
}

// ---------------- freqs ----------------
__global__ void init_freqs_kernel(const float* __restrict__ theta){
    int i = threadIdx.x;
    if (i < 32){
        double E = 2595.0 * log10(21.0);
        double v = (i == 31) ? E : (E/31.0) * (double)i;
        double mel = pow(10.0, v/2595.0) - 1.0;
        float fb = (float)(200.0 * mel / 1000.0);
        g_freqs[i] = (theta[0] / 220.0f) * fb;
    }
}

// ---------------- layernorm: writes bf16 hi/lo split directly ------------------------
__global__ void __launch_bounds__(256) ln_kernel(const float* __restrict__ x,
                                                 const float* __restrict__ lw,
                                                 const float* __restrict__ lb){
    int row = blockIdx.x;
    int t = threadIdx.x;
    const float4* xr = (const float4*)(x + (size_t)row * Dd);
    float4 v = xr[t];
    float s  = v.x + v.y + v.z + v.w;
    float s2 = v.x*v.x + v.y*v.y + v.z*v.z + v.w*v.w;
    __shared__ float shs[8], shs2[8], mv[2];
    #pragma unroll
    for (int o = 16; o > 0; o >>= 1){
        s  += __shfl_down_sync(0xffffffffu, s,  o);
        s2 += __shfl_down_sync(0xffffffffu, s2, o);
    }
    if ((t & 31) == 0){ shs[t>>5] = s; shs2[t>>5] = s2; }
    __syncthreads();
    if (t == 0){
        float a = 0.f, b2 = 0.f;
        #pragma unroll
        for (int i = 0; i < 8; i++){ a += shs[i]; b2 += shs2[i]; }
        float mu  = a  * (1.0f/Dd);
        float var = b2 * (1.0f/Dd) - mu*mu;
        mv[0] = mu; mv[1] = rsqrtf(var + 1e-5f);
    }
    __syncthreads();
    float mu = mv[0], rstd = mv[1];
    float4 w4 = ((const float4*)lw)[t];
    float4 b4 = ((const float4*)lb)[t];
    float4 o;
    o.x = (v.x - mu) * rstd * w4.x + b4.x;
    o.y = (v.y - mu) * rstd * w4.y + b4.y;
    o.z = (v.z - mu) * rstd * w4.z + b4.z;
    o.w = (v.w - mu) * rstd * w4.w + b4.w;
    float lx, ly, lz, lw2;
    uint32_t h01 = pk_hi(o.x, o.y, lx, ly);
    uint32_t h23 = pk_hi(o.z, o.w, lz, lw2);
    size_t idx = (size_t)row * (Dd/4) + t;
    ((uint2*)g_xnh)[idx] = make_uint2(h01, h23);
    ((uint2*)g_xnl)[idx] = make_uint2(pk(lx, ly), pk(lz, lw2));
}

// ---------------- RoPE + head split (+sc) ----------------
__global__ void rope_kernel(){
    int idx = blockIdx.x * blockDim.x + threadIdx.x;
    int m = idx & 31;
    int t = idx >> 5;
    int h = t & (Hh-1); t >>= 4;
    int c = t & (Cc-1);
    int b = t >> 11;
    float f   = g_freqs[m];
    float ang = (float)c * f;
    float sn = sinf(ang), cs = cosf(ang);
    size_t qoff  = ((size_t)(b*Cc + c)) * Dd     + h*HDd + 2*m;
    size_t kvoff = ((size_t)(b*Cc + c)) * (2*Dd) + h*HDd + 2*m;
    float qe = g_q[qoff],        qo = g_q[qoff+1];
    float ke = g_kv[kvoff],      ko = g_kv[kvoff+1];
    float ve = g_kv[kvoff + Dd], vo = g_kv[kvoff + Dd + 1];
    size_t ooff = ((size_t)((b*Hh + h)*Cc + c)) * HDd + 2*m;
    g_Q[ooff]   = qe*cs - qo*sn;
    g_Q[ooff+1] = qe*sn + qo*cs;
    float k0 = ke*cs - ko*sn;
    g_K[ooff]   = k0;
    g_K[ooff+1] = ke*sn + ko*cs;
    g_V[ooff]   = ve;
    g_V[ooff+1] = vo;
    if (m == 0) g_sc[(b*Hh + h)*Cc + c] = (k0 == 0.0f) ? 1e-5f : 1.0f;
}

// ---------------- Vsum per (b,h) ----------------
__global__ void __launch_bounds__(256) vsum_kernel(){
    int bh = blockIdx.x;
    int t = threadIdx.x;
    int d = t & 63, sl = t >> 6;
    const float* Vp = g_V + ((size_t)bh*Cc + sl*512) * HDd + d;
    float s = 0.f;
    #pragma unroll 8
    for (int j = 0; j < 512; j++) s += Vp[(size_t)j * HDd];
    __shared__ float sh[256];
    sh[t] = s;
    __syncthreads();
    if (t < 64)
        g_vsum[bh*64 + t] = sh[t] + sh[t+64] + sh[t+128] + sh[t+192];
}

// ---------------- attention: 64q x 64k tiles, causal only + Vsum rescue -------------
__global__ void __launch_bounds__(256) attn_kernel(const int* __restrict__ use_mask_p){
    extern __shared__ float sm[];
    float* Qs   = sm;
    float* Ks   = sm + 64*65;
    float* Vs   = sm + 2*64*65;
    float* rsum = Vs + 64*64;
    float* scs  = rsum + 64;

    int tid = threadIdx.x;
    int qb = blockIdx.x, bh = blockIdx.y;
    int b = bh >> 4, h = bh & 15;
    int i0 = qb * 64;
    int umask = use_mask_p[0];

    const float* Qg = g_Q + ((size_t)bh*Cc + i0) * HDd;
    for (int v = tid; v < 1024; v += 256){
        int r = v >> 4, c4 = (v & 15) * 4;
        float4 q4 = *(const float4*)(Qg + r*HDd + c4);
        Qs[r*65+c4] = q4.x; Qs[r*65+c4+1] = q4.y; Qs[r*65+c4+2] = q4.z; Qs[r*65+c4+3] = q4.w;
    }
    if (tid < 64) rsum[tid] = 0.f;

    float acc[4][4];
    #pragma unroll
    for (int i = 0; i < 4; i++)
        #pragma unroll
        for (int j = 0; j < 4; j++) acc[i][j] = 0.f;

    int ty = tid >> 4, tx = tid & 15;
    int r0 = ty*4, c0 = tx*4;
    int kb_last = umask ? qb : (Cc/64 - 1);

    for (int kb = 0; kb <= kb_last; kb++){
        int j0 = kb * 64;
        __syncthreads();
        const float* Kg = g_K + ((size_t)bh*Cc + j0) * HDd;
        const float* Vg = g_V + ((size_t)bh*Cc + j0) * HDd;
        for (int v = tid; v < 1024; v += 256){
            int r = v >> 4, c4 = (v & 15) * 4;
            float4 k4 = *(const float4*)(Kg + r*HDd + c4);
            Ks[r*65+c4] = k4.x; Ks[r*65+c4+1] = k4.y; Ks[r*65+c4+2] = k4.z; Ks[r*65+c4+3] = k4.w;
            float4 v4 = *(const float4*)(Vg + r*HDd + c4);
            *(float4*)(Vs + r*64 + c4) = v4;
        }
        if (tid < 64) scs[tid] = g_sc[(size_t)bh*Cc + j0 + tid];
        __syncthreads();

        float sv[4][4];
        #pragma unroll
        for (int i = 0; i < 4; i++)
            #pragma unroll
            for (int j = 0; j < 4; j++) sv[i][j] = 0.f;
        #pragma unroll 8
        for (int d = 0; d < 64; d++){
            float qr[4], kc[4];
            #pragma unroll
            for (int i = 0; i < 4; i++) qr[i] = Qs[(r0+i)*65 + d];
            #pragma unroll
            for (int j = 0; j < 4; j++) kc[j] = Ks[(c0+j)*65 + d];
            #pragma unroll
            for (int i = 0; i < 4; i++)
                #pragma unroll
                for (int j = 0; j < 4; j++)
                    sv[i][j] = fmaf(qr[i], kc[j], sv[i][j]);
        }
        __syncthreads();

        #pragma unroll
        for (int i = 0; i < 4; i++){
            int ig = i0 + r0 + i;
            #pragma unroll
            for (int j = 0; j < 4; j++){
                int jg = j0 + c0 + j;
                float scj = scs[c0+j];
                float val = sv[i][j] * 0.125f;
                if (umask){
                    if (jg > ig) val = -FLT_MAX;
                    val *= scj;
                    val = 1.0f / (1.0f + expf(-val));
                }
                val *= scj;
                float w = val + 0.5f*val*val;
                Ks[(r0+i)*65 + (c0+j)] = w;
            }
        }
        __syncthreads();

        if (tid < 64){
            float rs = 0.f;
            #pragma unroll 8
            for (int j = 0; j < 64; j++) rs += Ks[tid*65 + j];
            rsum[tid] += rs;
        }
        #pragma unroll 8
        for (int jc = 0; jc < 64; jc++){
            float wr[4], vc[4];
            #pragma unroll
            for (int i = 0; i < 4; i++) wr[i] = Ks[(r0+i)*65 + jc];
            #pragma unroll
            for (int j = 0; j < 4; j++) vc[j] = Vs[jc*64 + c0 + j];
            #pragma unroll
            for (int i = 0; i < 4; i++)
                #pragma unroll
                for (int j = 0; j < 4; j++)
                    acc[i][j] = fmaf(wr[i], vc[j], acc[i][j]);
        }
    }
    __syncthreads();

    const float* vs = g_vsum + bh*64;
    #pragma unroll
    for (int i = 0; i < 4; i++){
        int ig = i0 + r0 + i;
        float den = (float)Cc + rsum[r0+i];
        #pragma unroll
        for (int j = 0; j < 4; j++){
            float o = (vs[c0+j] + acc[i][j]) / den;
            g_wv[((size_t)(b*Cc + ig)) * Dd + h*HDd + c0 + j] = o;
        }
    }
}

// ---------------- launch ----------------
extern "C" void kernel_launch(void* const* d_in, const int* in_sizes, int n_in,
                              void* d_out, int out_size){
    const float* x    = (const float*)d_in[0];
    const float* lw   = (const float*)d_in[1];
    const float* lb   = (const float*)d_in[2];
    const float* Wq   = (const float*)d_in[3];
    const float* Wkv  = (const float*)d_in[4];
    const float* Wout = (const float*)d_in[5];
    const float* th   = (const float*)d_in[6];
    const int*   um   = (const int*)d_in[7];
    float* out = (float*)d_out;

    void *pxnh=0,*pxnl=0,*pwqh=0,*pwql=0,*pwkvh=0,*pwkvl=0,*pwoh=0,*pwol=0;
    void *pq=0,*pkv=0,*pwv=0,*pwvh=0,*pwvl=0;
    cudaGetSymbolAddress(&pxnh, g_xnh);  cudaGetSymbolAddress(&pxnl, g_xnl);
    cudaGetSymbolAddress(&pwqh, g_Wqh);  cudaGetSymbolAddress(&pwql, g_Wql);
    cudaGetSymbolAddress(&pwkvh, g_Wkvh); cudaGetSymbolAddress(&pwkvl, g_Wkvl);
    cudaGetSymbolAddress(&pwoh, g_Woh);  cudaGetSymbolAddress(&pwol, g_Wol);
    cudaGetSymbolAddress(&pq,  g_q);     cudaGetSymbolAddress(&pkv, g_kv);
    cudaGetSymbolAddress(&pwv, g_wv);
    cudaGetSymbolAddress(&pwvh, g_wvh);  cudaGetSymbolAddress(&pwvl, g_wvl);

    const int ATT_SMEM = (2*64*65 + 64*64 + 128) * 4;
    cudaFuncSetAttribute(attn_kernel, cudaFuncAttributeMaxDynamicSharedMemorySize, ATT_SMEM);
    cudaFuncSetAttribute(gemm_mma, cudaFuncAttributeMaxDynamicSharedMemorySize, GEMM_SMEM);

    init_freqs_kernel<<<1, 32>>>(th);
    cvt_kernel<<<(Dd*Dd)/1024,   256>>>(Wq,   (bf16*)pwqh,  (bf16*)pwql);
    cvt_kernel<<<(2*Dd*Dd)/1024, 256>>>(Wkv,  (bf16*)pwkvh, (bf16*)pwkvl);
    cvt_kernel<<<(Dd*Dd)/1024,   256>>>(Wout, (bf16*)pwoh,  (bf16*)pwol);
    ln_kernel<<<ROWS, 256>>>(x, lw, lb);

    gemm_mma<<<dim3(Dd/128,   ROWS/128), 256, GEMM_SMEM>>>(
        (const bf16*)pxnh, (const bf16*)pxnl, (const bf16*)pwqh,  (const bf16*)pwql,  (float*)pq,  Dd);
    gemm_mma<<<dim3(2*Dd/128, ROWS/128), 256, GEMM_SMEM>>>(
        (const bf16*)pxnh, (const bf16*)pxnl, (const bf16*)pwkvh, (const bf16*)pwkvl, (float*)pkv, 2*Dd);

    rope_kernel<<<(Bb*Hh*Cc*32)/256, 256>>>();
    vsum_kernel<<<Bb*Hh, 256>>>();
    attn_kernel<<<dim3(Cc/64, Bb*Hh), 256, ATT_SMEM>>>(um);

    cvt_kernel<<<(ROWS*Dd)/1024, 256>>>((const float*)pwv, (bf16*)pwvh, (bf16*)pwvl);
    gemm_mma<<<dim3(Dd/128, ROWS/128), 256, GEMM_SMEM>>>(
        (const bf16*)pwvh, (const bf16*)pwvl, (const bf16*)pwoh, (const bf16*)pwol, out, Dd);
}

// round 5
// speedup vs baseline: 2.2733x; 1.4118x over previous
#include <cuda_runtime.h>
#include <cuda_bf16.h>
#include <math.h>
#include <float.h>
#include <stdint.h>

#define Bb   2
#define Cc   2048
#define Dd   1024
#define Hh   16
#define HDd  64
#define ROWS (Bb*Cc)   // 4096

typedef __nv_bfloat16 bf16;

// ---------------- scratch ----------------
__device__ float g_q [ROWS*Dd];
__device__ float g_kv[ROWS*2*Dd];
__device__ float g_sc[Bb*Hh*Cc];
__device__ float g_vsum[Bb*Hh*HDd];
__device__ float g_freqs[HDd/2];

__device__ bf16 g_xnh[ROWS*Dd],  g_xnl[ROWS*Dd];
__device__ bf16 g_wvh[ROWS*Dd],  g_wvl[ROWS*Dd];
__device__ bf16 g_Wqh[Dd*Dd],    g_Wql[Dd*Dd];
__device__ bf16 g_Wkvh[2*Dd*Dd], g_Wkvl[2*Dd*Dd];
__device__ bf16 g_Woh[Dd*Dd],    g_Wol[Dd*Dd];
__device__ bf16 g_Qh[Bb*Hh*Cc*HDd], g_Ql[Bb*Hh*Cc*HDd];
__device__ bf16 g_Kh[Bb*Hh*Cc*HDd], g_Kl[Bb*Hh*Cc*HDd];
__device__ bf16 g_Vh[Bb*Hh*Cc*HDd], g_Vl[Bb*Hh*Cc*HDd];

// ================= PTX helpers =================
__device__ __forceinline__ uint32_t smem_u32(const void* p){
    uint32_t a;
    asm("{ .reg .u64 t; cvta.to.shared.u64 t, %1; cvt.u32.u64 %0, t; }" : "=r"(a) : "l"(p));
    return a;
}
#define CP16(dst, src) asm volatile("cp.async.cg.shared.global [%0], [%1], 16;" :: "r"(dst), "l"(src) : "memory")
#define CP_COMMIT()    asm volatile("cp.async.commit_group;" ::: "memory")
#define CP_WAIT(n)     asm volatile("cp.async.wait_group %0;" :: "n"(n) : "memory")
#define LDSM4(r, a) asm volatile("ldmatrix.sync.aligned.m8n8.x4.shared.b16 {%0,%1,%2,%3}, [%4];" \
  : "=r"((r)[0]),"=r"((r)[1]),"=r"((r)[2]),"=r"((r)[3]) : "r"(a))
#define LDSM4T(r, a) asm volatile("ldmatrix.sync.aligned.m8n8.x4.trans.shared.b16 {%0,%1,%2,%3}, [%4];" \
  : "=r"((r)[0]),"=r"((r)[1]),"=r"((r)[2]),"=r"((r)[3]) : "r"(a))
#define MMA4(c, a, b0, b1) asm volatile( \
  "mma.sync.aligned.m16n8k16.row.col.f32.bf16.bf16.f32 {%0,%1,%2,%3}, {%4,%5,%6,%7}, {%8,%9}, {%0,%1,%2,%3};" \
  : "+f"((c)[0]),"+f"((c)[1]),"+f"((c)[2]),"+f"((c)[3]) \
  : "r"((a)[0]),"r"((a)[1]),"r"((a)[2]),"r"((a)[3]), "r"(b0),"r"(b1))

__device__ __forceinline__ uint32_t swz(uint32_t bo){ return bo ^ ((bo >> 3) & 0x70); }

__device__ __forceinline__ uint32_t pk_hi(float x, float y, float& lx, float& ly){
    bf16 hx = __float2bfloat16(x);
    bf16 hy = __float2bfloat16(y);
    lx = x - __bfloat162float(hx);
    ly = y - __bfloat162float(hy);
    return (uint32_t)__bfloat16_as_ushort(hx) | ((uint32_t)__bfloat16_as_ushort(hy) << 16);
}
__device__ __forceinline__ uint32_t pk(float x, float y){
    bf16 hx = __float2bfloat16(x);
    bf16 hy = __float2bfloat16(y);
    return (uint32_t)__bfloat16_as_ushort(hx) | ((uint32_t)__bfloat16_as_ushort(hy) << 16);
}

// ---------------- fp32 -> bf16 hi/lo split ----------------
__global__ void __launch_bounds__(256) cvt_kernel(const float* __restrict__ src,
                                                  bf16* __restrict__ h, bf16* __restrict__ l){
    int i = blockIdx.x * 256 + threadIdx.x;
    float4 a = ((const float4*)src)[i];
    float lx, ly, lz, lw;
    uint32_t h01 = pk_hi(a.x, a.y, lx, ly);
    uint32_t h23 = pk_hi(a.z, a.w, lz, lw);
    ((uint2*)h)[i] = make_uint2(h01, h23);
    ((uint2*)l)[i] = make_uint2(pk(lx, ly), pk(lz, lw));
}

// ================= bf16x3 mma.sync GEMM (validated R4) ==============================
#define GEMM_SMEM (2*65536)

__device__ __forceinline__ void issue_stage(uint32_t sb, int s, int c, int tid,
                                            const bf16* Ah, const bf16* Al,
                                            const bf16* Bh, const bf16* Bl,
                                            int m0, int n0){
    const bf16* srcs[4] = {Ah, Al, Bh, Bl};
    #pragma unroll
    for (int bufi = 0; bufi < 4; bufi++){
        int row0 = (bufi < 2) ? m0 : n0;
        const bf16* S = srcs[bufi];
        uint32_t dstb = sb + s*65536 + bufi*16384;
        #pragma unroll
        for (int it = 0; it < 4; it++){
            int i = tid + it*256;
            int r  = i >> 3;
            int cb = (i & 7) * 16;
            uint32_t dst = dstb + swz((uint32_t)(r*128 + cb));
            const char* src = (const char*)(S + (size_t)(row0 + r)*1024 + c*64) + cb;
            CP16(dst, src);
        }
    }
}

__global__ void __launch_bounds__(256) gemm_mma(const bf16* __restrict__ Ah,
                                                const bf16* __restrict__ Al,
                                                const bf16* __restrict__ Bh,
                                                const bf16* __restrict__ Bl,
                                                float* __restrict__ C, int N){
    extern __shared__ __align__(1024) char smem[];
    uint32_t sb = smem_u32(smem);
    int tid = threadIdx.x, lane = tid & 31, wid = tid >> 5;
    int m0 = blockIdx.y * 128, n0 = blockIdx.x * 128;
    int wm = (wid >> 2) * 64;
    int wn = (wid & 3) * 32;

    float acc[4][4][4];
    #pragma unroll
    for (int a = 0; a < 4; a++)
        #pragma unroll
        for (int b = 0; b < 4; b++)
            #pragma unroll
            for (int c = 0; c < 4; c++) acc[a][b][c] = 0.f;

    issue_stage(sb, 0, 0, tid, Ah, Al, Bh, Bl, m0, n0);
    CP_COMMIT();

    #pragma unroll 1
    for (int c = 0; c < 16; c++){
        if (c + 1 < 16){
            issue_stage(sb, (c+1)&1, c+1, tid, Ah, Al, Bh, Bl, m0, n0);
            CP_COMMIT();
            CP_WAIT(1);
        } else {
            CP_WAIT(0);
        }
        __syncthreads();

        uint32_t sA = sb + (c&1)*65536;
        uint32_t sB = sA + 32768;
        #pragma unroll
        for (int ks = 0; ks < 4; ks++){
            uint32_t ahf[4][4], alf[4][4], bhf[2][4], blf[2][4];
            #pragma unroll
            for (int mt = 0; mt < 4; mt++){
                int r    = wm + mt*16 + (lane & 7) + ((lane >> 3) & 1)*8;
                int koff = ks*32 + (lane >> 4)*16;
                uint32_t sw = swz((uint32_t)(r*128 + koff));
                LDSM4(ahf[mt], sA + sw);
                LDSM4(alf[mt], sA + 16384 + sw);
            }
            #pragma unroll
            for (int p = 0; p < 2; p++){
                int r    = wn + p*16 + ((lane >> 4) & 1)*8 + (lane & 7);
                int koff = ks*32 + ((lane >> 3) & 1)*16;
                uint32_t sw = swz((uint32_t)(r*128 + koff));
                LDSM4(bhf[p], sB + sw);
                LDSM4(blf[p], sB + 16384 + sw);
            }
            #pragma unroll
            for (int mt = 0; mt < 4; mt++)
                #pragma unroll
                for (int nt = 0; nt < 4; nt++){
                    int p = nt >> 1, s2 = nt & 1;
                    MMA4(acc[mt][nt], ahf[mt], bhf[p][s2*2], bhf[p][s2*2+1]);
                    MMA4(acc[mt][nt], ahf[mt], blf[p][s2*2], blf[p][s2*2+1]);
                    MMA4(acc[mt][nt], alf[mt], bhf[p][s2*2], bhf[p][s2*2+1]);
                }
        }
        __syncthreads();
    }

    #pragma unroll
    for (int mt = 0; mt < 4; mt++){
        #pragma unroll
        for (int nt = 0; nt < 4; nt++){
            int row = m0 + wm + mt*16 + (lane >> 2);
            int col = n0 + wn + nt*8  + (lane & 3)*2;
            float2 v0 = { acc[mt][nt][0], acc[mt][nt][1] };
            float2 v1 = { acc[mt][nt][2], acc[mt][nt][3] };
            *(float2*)(C + (size_t)row*N + col)     = v0;
            *(float2*)(C + (size_t)(row+8)*N + col) = v1;
        }
    }
}

// ---------------- freqs ----------------
__global__ void init_freqs_kernel(const float* __restrict__ theta){
    int i = threadIdx.x;
    if (i < 32){
        double E = 2595.0 * log10(21.0);
        double v = (i == 31) ? E : (E/31.0) * (double)i;
        double mel = pow(10.0, v/2595.0) - 1.0;
        float fb = (float)(200.0 * mel / 1000.0);
        g_freqs[i] = (theta[0] / 220.0f) * fb;
    }
}

// ---------------- layernorm -> bf16 hi/lo ----------------
__global__ void __launch_bounds__(256) ln_kernel(const float* __restrict__ x,
                                                 const float* __restrict__ lw,
                                                 const float* __restrict__ lb){
    int row = blockIdx.x;
    int t = threadIdx.x;
    const float4* xr = (const float4*)(x + (size_t)row * Dd);
    float4 v = xr[t];
    float s  = v.x + v.y + v.z + v.w;
    float s2 = v.x*v.x + v.y*v.y + v.z*v.z + v.w*v.w;
    __shared__ float shs[8], shs2[8], mv[2];
    #pragma unroll
    for (int o = 16; o > 0; o >>= 1){
        s  += __shfl_down_sync(0xffffffffu, s,  o);
        s2 += __shfl_down_sync(0xffffffffu, s2, o);
    }
    if ((t & 31) == 0){ shs[t>>5] = s; shs2[t>>5] = s2; }
    __syncthreads();
    if (t == 0){
        float a = 0.f, b2 = 0.f;
        #pragma unroll
        for (int i = 0; i < 8; i++){ a += shs[i]; b2 += shs2[i]; }
        float mu  = a  * (1.0f/Dd);
        float var = b2 * (1.0f/Dd) - mu*mu;
        mv[0] = mu; mv[1] = rsqrtf(var + 1e-5f);
    }
    __syncthreads();
    float mu = mv[0], rstd = mv[1];
    float4 w4 = ((const float4*)lw)[t];
    float4 b4 = ((const float4*)lb)[t];
    float4 o;
    o.x = (v.x - mu) * rstd * w4.x + b4.x;
    o.y = (v.y - mu) * rstd * w4.y + b4.y;
    o.z = (v.z - mu) * rstd * w4.z + b4.z;
    o.w = (v.w - mu) * rstd * w4.w + b4.w;
    float lx, ly, lz, lw2;
    uint32_t h01 = pk_hi(o.x, o.y, lx, ly);
    uint32_t h23 = pk_hi(o.z, o.w, lz, lw2);
    size_t idx = (size_t)row * (Dd/4) + t;
    ((uint2*)g_xnh)[idx] = make_uint2(h01, h23);
    ((uint2*)g_xnl)[idx] = make_uint2(pk(lx, ly), pk(lz, lw2));
}

// ---------------- RoPE + head split, writes bf16 hi/lo (+sc) ------------------------
__global__ void rope_kernel(){
    int idx = blockIdx.x * blockDim.x + threadIdx.x;
    int m = idx & 31;
    int t = idx >> 5;
    int h = t & (Hh-1); t >>= 4;
    int c = t & (Cc-1);
    int b = t >> 11;
    float f   = g_freqs[m];
    float ang = (float)c * f;
    float sn = sinf(ang), cs = cosf(ang);
    size_t qoff  = ((size_t)(b*Cc + c)) * Dd     + h*HDd + 2*m;
    size_t kvoff = ((size_t)(b*Cc + c)) * (2*Dd) + h*HDd + 2*m;
    float qe = g_q[qoff],        qo = g_q[qoff+1];
    float ke = g_kv[kvoff],      ko = g_kv[kvoff+1];
    float ve = g_kv[kvoff + Dd], vo = g_kv[kvoff + Dd + 1];
    size_t ooff = ((size_t)((b*Hh + h)*Cc + c)) * HDd + 2*m;
    // Q with 1/sqrt(64)=0.125 folded in (exact pow2 scale)
    float q0 = 0.125f*(qe*cs - qo*sn);
    float q1 = 0.125f*(qe*sn + qo*cs);
    float k0 = ke*cs - ko*sn;
    float k1 = ke*sn + ko*cs;
    float lx, ly;
    *(uint32_t*)(g_Qh + ooff) = pk_hi(q0, q1, lx, ly);
    *(uint32_t*)(g_Ql + ooff) = pk(lx, ly);
    *(uint32_t*)(g_Kh + ooff) = pk_hi(k0, k1, lx, ly);
    *(uint32_t*)(g_Kl + ooff) = pk(lx, ly);
    *(uint32_t*)(g_Vh + ooff) = pk_hi(ve, vo, lx, ly);
    *(uint32_t*)(g_Vl + ooff) = pk(lx, ly);
    if (m == 0) g_sc[(b*Hh + h)*Cc + c] = (k0 == 0.0f) ? 1e-5f : 1.0f;
}

// ---------------- Vsum per (b,h) from split V ----------------------------------------
__global__ void __launch_bounds__(256) vsum_kernel(){
    int bh = blockIdx.x;
    int t = threadIdx.x;
    int d = t & 63, sl = t >> 6;
    const bf16* Vh = g_Vh + ((size_t)bh*Cc + sl*512) * HDd + d;
    const bf16* Vl = g_Vl + ((size_t)bh*Cc + sl*512) * HDd + d;
    float s = 0.f;
    #pragma unroll 8
    for (int j = 0; j < 512; j++)
        s += __bfloat162float(Vh[(size_t)j * HDd]) + __bfloat162float(Vl[(size_t)j * HDd]);
    __shared__ float sh[256];
    sh[t] = s;
    __syncthreads();
    if (t < 64)
        g_vsum[bh*64 + t] = sh[t] + sh[t+64] + sh[t+128] + sh[t+192];
}

// ================= attention: mma.sync flash kernel =================================
// grid (16, 32), block 256 (8 warps x 16 q-rows). Tiles 128q x 64k.
// smem stage (33024 B): Kh 8K | Kl 8K | Vh 8K | Vl 8K | sc 256B. Two stages.
#define ATT_SMEM (2*33024)

__device__ __forceinline__ void issue_kv(uint32_t sb, int s, int j0, int bh, int tid){
    uint32_t stb = sb + s*33024;
    const bf16* srcs[4] = { g_Kh + ((size_t)bh*Cc + j0)*HDd, g_Kl + ((size_t)bh*Cc + j0)*HDd,
                            g_Vh + ((size_t)bh*Cc + j0)*HDd, g_Vl + ((size_t)bh*Cc + j0)*HDd };
    #pragma unroll
    for (int bufi = 0; bufi < 4; bufi++){
        const bf16* S = srcs[bufi];
        uint32_t dstb = stb + bufi*8192;
        #pragma unroll
        for (int it = 0; it < 2; it++){
            int i = tid + it*256;          // 0..511 chunks of 16B (64 rows x 8)
            int r  = i >> 3;
            int cb = (i & 7) * 16;
            uint32_t dst = dstb + swz((uint32_t)(r*128 + cb));
            CP16(dst, (const char*)S + r*128 + cb);
        }
    }
    if (tid < 16)
        CP16(stb + 32768 + tid*16, (const char*)(g_sc + (size_t)bh*Cc + j0) + tid*16);
}

__global__ void __launch_bounds__(256) attn_mma(const int* __restrict__ um_p){
    extern __shared__ __align__(1024) char smc[];
    uint32_t sb = smem_u32(smc);
    int tid = threadIdx.x, lane = tid & 31, wid = tid >> 5;
    int qb = blockIdx.x, bh = blockIdx.y;
    int b = bh >> 4, h = bh & 15;
    int i0 = qb * 128;
    int wm = wid * 16;
    int umask = um_p[0];

    // ---- load Q tile (128 x 64, hi/lo) into smem, then frags ----
    {
        const bf16* Qhg = g_Qh + ((size_t)bh*Cc + i0)*HDd;
        const bf16* Qlg = g_Ql + ((size_t)bh*Cc + i0)*HDd;
        #pragma unroll
        for (int it = 0; it < 4; it++){
            int i = tid + it*256;          // 0..1023 chunks (128 rows x 8)
            int r  = i >> 3;
            int cb = (i & 7) * 16;
            uint32_t sw = swz((uint32_t)(r*128 + cb));
            CP16(sb + sw,         (const char*)Qhg + r*128 + cb);
            CP16(sb + 16384 + sw, (const char*)Qlg + r*128 + cb);
        }
        CP_COMMIT(); CP_WAIT(0);
        __syncthreads();
    }
    uint32_t qh[4][4], ql[4][4];
    #pragma unroll
    for (int ks = 0; ks < 4; ks++){
        int r    = wm + (lane & 7) + ((lane >> 3) & 1)*8;
        int koff = ks*32 + (lane >> 4)*16;
        uint32_t sw = swz((uint32_t)(r*128 + koff));
        LDSM4(qh[ks], sb + sw);
        LDSM4(ql[ks], sb + 16384 + sw);
    }
    __syncthreads();

    float oacc[8][4];
    #pragma unroll
    for (int nt = 0; nt < 8; nt++)
        #pragma unroll
        for (int e = 0; e < 4; e++) oacc[nt][e] = 0.f;
    float rs0 = 0.f, rs1 = 0.f;

    int ig0 = i0 + wm + (lane >> 2);
    int ig1 = ig0 + 8;
    int kb_last = umask ? (2*qb + 1) : (Cc/64 - 1);

    issue_kv(sb, 0, 0, bh, tid);
    CP_COMMIT();

    #pragma unroll 1
    for (int kb = 0; kb <= kb_last; kb++){
        int s = kb & 1;
        int j0 = kb * 64;
        if (kb < kb_last){
            issue_kv(sb, s^1, j0 + 64, bh, tid);
            CP_COMMIT();
            CP_WAIT(1);
        } else {
            CP_WAIT(0);
        }
        __syncthreads();

        uint32_t stb = sb + s*33024;

        // ---- S = Q K^T (bf16x3, fp32 accum) ----
        float sacc[8][4];
        #pragma unroll
        for (int nt = 0; nt < 8; nt++)
            #pragma unroll
            for (int e = 0; e < 4; e++) sacc[nt][e] = 0.f;
        #pragma unroll
        for (int ks = 0; ks < 4; ks++){
            #pragma unroll
            for (int p = 0; p < 4; p++){
                int r    = p*16 + ((lane >> 4) & 1)*8 + (lane & 7);
                int koff = ks*32 + ((lane >> 3) & 1)*16;
                uint32_t sw = swz((uint32_t)(r*128 + koff));
                uint32_t kh4[4], kl4[4];
                LDSM4(kh4, stb + sw);
                LDSM4(kl4, stb + 8192 + sw);
                MMA4(sacc[2*p],   qh[ks], kh4[0], kh4[1]);
                MMA4(sacc[2*p],   qh[ks], kl4[0], kl4[1]);
                MMA4(sacc[2*p],   ql[ks], kh4[0], kh4[1]);
                MMA4(sacc[2*p+1], qh[ks], kh4[2], kh4[3]);
                MMA4(sacc[2*p+1], qh[ks], kl4[2], kl4[3]);
                MMA4(sacc[2*p+1], ql[ks], kh4[2], kh4[3]);
            }
        }

        // ---- elementwise -> w, row sums ----
        const float* scp = (const float*)(smc + s*33024 + 32768);
        #pragma unroll
        for (int nt = 0; nt < 8; nt++){
            int jc = nt*8 + (lane & 3)*2;
            float2 sc2 = *(const float2*)(scp + jc);
            #pragma unroll
            for (int e = 0; e < 4; e++){
                int jg = j0 + jc + (e & 1);
                int ig = (e < 2) ? ig0 : ig1;
                float scj = (e & 1) ? sc2.y : sc2.x;
                float val = sacc[nt][e];
                if (umask){
                    if (jg > ig) val = -FLT_MAX;
                    val *= scj;
                    val = 1.0f / (1.0f + expf(-val));
                }
                val *= scj;
                float w = val + 0.5f*val*val;
                sacc[nt][e] = w;
                if (e < 2) rs0 += w; else rs1 += w;
            }
        }

        // ---- O += W V (bf16x3) ----
        #pragma unroll
        for (int pk2 = 0; pk2 < 4; pk2++){
            uint32_t awh[4], awl[4];
            float l0, l1;
            awh[0] = pk_hi(sacc[2*pk2][0],   sacc[2*pk2][1],   l0, l1); awl[0] = pk(l0, l1);
            awh[1] = pk_hi(sacc[2*pk2][2],   sacc[2*pk2][3],   l0, l1); awl[1] = pk(l0, l1);
            awh[2] = pk_hi(sacc[2*pk2+1][0], sacc[2*pk2+1][1], l0, l1); awl[2] = pk(l0, l1);
            awh[3] = pk_hi(sacc[2*pk2+1][2], sacc[2*pk2+1][3], l0, l1); awl[3] = pk(l0, l1);
            #pragma unroll
            for (int dc = 0; dc < 4; dc++){
                int r  = pk2*16 + (lane & 7) + ((lane >> 3) & 1)*8;
                int cb = dc*32 + ((lane >> 4) & 1)*16;
                uint32_t sw = swz((uint32_t)(r*128 + cb));
                uint32_t vh4[4], vl4[4];
                LDSM4T(vh4, stb + 16384 + sw);
                LDSM4T(vl4, stb + 24576 + sw);
                MMA4(oacc[2*dc],   awh, vh4[0], vh4[1]);
                MMA4(oacc[2*dc],   awh, vl4[0], vl4[1]);
                MMA4(oacc[2*dc],   awl, vh4[0], vh4[1]);
                MMA4(oacc[2*dc+1], awh, vh4[2], vh4[3]);
                MMA4(oacc[2*dc+1], awh, vl4[2], vl4[3]);
                MMA4(oacc[2*dc+1], awl, vh4[2], vh4[3]);
            }
        }
        __syncthreads();
    }

    // ---- epilogue: quad-reduce row sums, add Vsum, normalize, write bf16 split ----
    rs0 += __shfl_xor_sync(0xffffffffu, rs0, 1);
    rs0 += __shfl_xor_sync(0xffffffffu, rs0, 2);
    rs1 += __shfl_xor_sync(0xffffffffu, rs1, 1);
    rs1 += __shfl_xor_sync(0xffffffffu, rs1, 2);
    float inv0 = 1.0f / ((float)Cc + rs0);
    float inv1 = 1.0f / ((float)Cc + rs1);

    const float* vsp = g_vsum + bh*64;
    size_t base0 = (size_t)(b*Cc + ig0) * Dd + h*HDd;
    size_t base1 = (size_t)(b*Cc + ig1) * Dd + h*HDd;
    #pragma unroll
    for (int nt = 0; nt < 8; nt++){
        int col = nt*8 + (lane & 3)*2;
        float2 vs = *(const float2*)(vsp + col);
        float o00 = (vs.x + oacc[nt][0]) * inv0;
        float o01 = (vs.y + oacc[nt][1]) * inv0;
        float o10 = (vs.x + oacc[nt][2]) * inv1;
        float o11 = (vs.y + oacc[nt][3]) * inv1;
        float l0, l1;
        uint32_t hh0 = pk_hi(o00, o01, l0, l1);
        uint32_t ll0 = pk(l0, l1);
        *(uint32_t*)(g_wvh + base0 + col) = hh0;
        *(uint32_t*)(g_wvl + base0 + col) = ll0;
        uint32_t hh1 = pk_hi(o10, o11, l0, l1);
        uint32_t ll1 = pk(l0, l1);
        *(uint32_t*)(g_wvh + base1 + col) = hh1;
        *(uint32_t*)(g_wvl + base1 + col) = ll1;
    }
}

// ---------------- launch ----------------
extern "C" void kernel_launch(void* const* d_in, const int* in_sizes, int n_in,
                              void* d_out, int out_size){
    const float* x    = (const float*)d_in[0];
    const float* lw   = (const float*)d_in[1];
    const float* lb   = (const float*)d_in[2];
    const float* Wq   = (const float*)d_in[3];
    const float* Wkv  = (const float*)d_in[4];
    const float* Wout = (const float*)d_in[5];
    const float* th   = (const float*)d_in[6];
    const int*   um   = (const int*)d_in[7];
    float* out = (float*)d_out;

    void *pxnh=0,*pxnl=0,*pwqh=0,*pwql=0,*pwkvh=0,*pwkvl=0,*pwoh=0,*pwol=0;
    void *pq=0,*pkv=0,*pwvh=0,*pwvl=0;
    cudaGetSymbolAddress(&pxnh, g_xnh);  cudaGetSymbolAddress(&pxnl, g_xnl);
    cudaGetSymbolAddress(&pwqh, g_Wqh);  cudaGetSymbolAddress(&pwql, g_Wql);
    cudaGetSymbolAddress(&pwkvh, g_Wkvh); cudaGetSymbolAddress(&pwkvl, g_Wkvl);
    cudaGetSymbolAddress(&pwoh, g_Woh);  cudaGetSymbolAddress(&pwol, g_Wol);
    cudaGetSymbolAddress(&pq,  g_q);     cudaGetSymbolAddress(&pkv, g_kv);
    cudaGetSymbolAddress(&pwvh, g_wvh);  cudaGetSymbolAddress(&pwvl, g_wvl);

    cudaFuncSetAttribute(gemm_mma, cudaFuncAttributeMaxDynamicSharedMemorySize, GEMM_SMEM);
    cudaFuncSetAttribute(attn_mma, cudaFuncAttributeMaxDynamicSharedMemorySize, ATT_SMEM);

    init_freqs_kernel<<<1, 32>>>(th);
    cvt_kernel<<<(Dd*Dd)/1024,   256>>>(Wq,   (bf16*)pwqh,  (bf16*)pwql);
    cvt_kernel<<<(2*Dd*Dd)/1024, 256>>>(Wkv,  (bf16*)pwkvh, (bf16*)pwkvl);
    cvt_kernel<<<(Dd*Dd)/1024,   256>>>(Wout, (bf16*)pwoh,  (bf16*)pwol);
    ln_kernel<<<ROWS, 256>>>(x, lw, lb);

    gemm_mma<<<dim3(Dd/128,   ROWS/128), 256, GEMM_SMEM>>>(
        (const bf16*)pxnh, (const bf16*)pxnl, (const bf16*)pwqh,  (const bf16*)pwql,  (float*)pq,  Dd);
    gemm_mma<<<dim3(2*Dd/128, ROWS/128), 256, GEMM_SMEM>>>(
        (const bf16*)pxnh, (const bf16*)pxnl, (const bf16*)pwkvh, (const bf16*)pwkvl, (float*)pkv, 2*Dd);

    rope_kernel<<<(Bb*Hh*Cc*32)/256, 256>>>();
    vsum_kernel<<<Bb*Hh, 256>>>();
    attn_mma<<<dim3(Cc/128, Bb*Hh), 256, ATT_SMEM>>>(um);

    gemm_mma<<<dim3(Dd/128, ROWS/128), 256, GEMM_SMEM>>>(
        (const bf16*)pwvh, (const bf16*)pwvl, (const bf16*)pwoh, (const bf16*)pwol, out, Dd);
}